// round 13
// baseline (speedup 1.0000x reference)
#include <cuda_runtime.h>
#include <cstdint>

#define RDIM 256
#define CDIM 32
#define NPTS 524288
#define THREADS 256
#define NWTILES (NPTS / 16)        // 32768 warp-tiles of 16 points

// Transposed triplanes scratch: [bp][y][x][c], fp32 (~100.7 MB)
__device__ float g_tp[(size_t)12 * RDIM * RDIM * CDIM];

// ---------------- smem layout (bytes) ----------------
// int8 weight rows padded: W1 row 128B data + 16 pad = 144 (16B offsets of 8
// ldsm rows distinct mod 128); W0/F/H rows 32B data + 16 pad = 48.
#define OFF_W1HI 0                  // 128 * 144
#define OFF_W1LO 18432
#define OFF_W0HI 36864              // 128 * 48
#define OFF_W0LO 43008
#define OFF_SW0  49152              // 128 f32
#define OFF_SW1  49664
#define OFF_B0   50176
#define OFF_B1   50688
#define OFF_W2   51200
#define OFF_FW   51712              // 8 warps * 3200: Fhi,Flo,Hhi,Hlo (768 ea) + sF(64)
#define SMEM_BYTES 77312

// ---------------- helpers ----------------
__device__ __forceinline__ uint32_t smem_u32(const void* p) {
    uint32_t a;
    asm("{ .reg .u64 t; cvta.to.shared.u64 t, %1; cvt.u32.u64 %0, t; }" : "=r"(a) : "l"(p));
    return a;
}
__device__ __forceinline__ void imma16832(int* d, const uint32_t* a, const uint32_t* b) {
    asm volatile("mma.sync.aligned.m16n8k32.row.col.s32.s8.s8.s32 "
                 "{%0,%1,%2,%3}, {%4,%5,%6,%7}, {%8,%9}, {%0,%1,%2,%3};"
                 : "+r"(d[0]), "+r"(d[1]), "+r"(d[2]), "+r"(d[3])
                 : "r"(a[0]), "r"(a[1]), "r"(a[2]), "r"(a[3]), "r"(b[0]), "r"(b[1]));
}
__device__ __forceinline__ void ldsm4(uint32_t* r, uint32_t addr) {
    asm volatile("ldmatrix.sync.aligned.m8n8.x4.shared.b16 {%0,%1,%2,%3}, [%4];"
                 : "=r"(r[0]), "=r"(r[1]), "=r"(r[2]), "=r"(r[3]) : "r"(addr));
}
__device__ __forceinline__ uint32_t pack4(int a, int b, int c, int d) {
    uint32_t x = __byte_perm((uint32_t)a, (uint32_t)b, 0x0040);
    uint32_t y = __byte_perm((uint32_t)c, (uint32_t)d, 0x0040);
    return __byte_perm(x, y, 0x5410);
}
// two-level int8 quantization of 4 values
__device__ __forceinline__ void quant8(float4 v, float inv, uint32_t& hi, uint32_t& lo) {
    float p0 = v.x * inv, p1 = v.y * inv, p2 = v.z * inv, p3 = v.w * inv;
    int h0 = __float2int_rn(p0), h1 = __float2int_rn(p1);
    int h2 = __float2int_rn(p2), h3 = __float2int_rn(p3);
    int l0 = __float2int_rn((p0 - (float)h0) * 254.f);
    int l1 = __float2int_rn((p1 - (float)h1) * 254.f);
    int l2 = __float2int_rn((p2 - (float)h2) * 254.f);
    int l3 = __float2int_rn((p3 - (float)h3) * 254.f);
    hi = pack4(h0, h1, h2, h3);
    lo = pack4(l0, l1, l2, l3);
}
#define C254 (1.0f / 254.0f)

// ---------- Kernel 1: transpose [bp][c][y][x] -> [bp][y][x][c] ----------
__global__ void transpose_planes(const float* __restrict__ in) {
    __shared__ float t[32][33];
    int tx = threadIdx.x, ty = threadIdx.y;
    int xb = blockIdx.x * 32, y = blockIdx.y, bp = blockIdx.z;
    const float* src = in + ((size_t)bp * CDIM) * (RDIM * RDIM) + (size_t)y * RDIM + xb;
#pragma unroll
    for (int i = 0; i < 4; i++) {
        int c = ty + i * 8;
        t[c][tx] = src[(size_t)c * (RDIM * RDIM) + tx];
    }
    __syncthreads();
    float* dst = g_tp + (((size_t)bp * RDIM + y) * RDIM + xb) * CDIM;
#pragma unroll
    for (int i = 0; i < 4; i++) {
        int xl = ty + i * 8;
        dst[(size_t)xl * CDIM + tx] = t[tx][xl];
    }
}

// ---------- Kernel 2: gather + int8 double-split IMMA MLP (2 CTAs/SM) ----------
__global__ __launch_bounds__(THREADS, 2)
void fused_triplane_mlp_i8(const float* __restrict__ coords,
                           const float* __restrict__ w0, const float* __restrict__ b0,
                           const float* __restrict__ w1, const float* __restrict__ b1,
                           const float* __restrict__ w2, const float* __restrict__ b2,
                           float* __restrict__ out) {
    extern __shared__ char sm[];
    const uint32_t sb = smem_u32(sm);
    const int tid = threadIdx.x;
    const int wid = tid >> 5;
    const int lane = tid & 31;

    float* sW0f = (float*)(sm + OFF_SW0);
    float* sW1f = (float*)(sm + OFF_SW1);
    float* sB0  = (float*)(sm + OFF_B0);
    float* sB1  = (float*)(sm + OFF_B1);
    float* sW2  = (float*)(sm + OFF_W2);

    // ---- stage weights: per-row int8 double-split + row scale ----
    if (tid < 128) {
        {   // W0 row j = tid (32 floats)
            const float4* src = (const float4*)(w0 + tid * 32);
            float mx = 0.f;
#pragma unroll
            for (int i = 0; i < 8; i++) {
                float4 v = src[i];
                mx = fmaxf(mx, fmaxf(fmaxf(fabsf(v.x), fabsf(v.y)), fmaxf(fabsf(v.z), fabsf(v.w))));
            }
            float inv = 127.f / fmaxf(mx, 1e-30f);
            sW0f[tid] = mx * (1.f / 127.f);
#pragma unroll
            for (int i = 0; i < 8; i++) {
                uint32_t hi, lo;
                quant8(src[i], inv, hi, lo);
                *(uint32_t*)(sm + OFF_W0HI + tid * 48 + i * 4) = hi;
                *(uint32_t*)(sm + OFF_W0LO + tid * 48 + i * 4) = lo;
            }
        }
        {   // W1 row g = tid (128 floats, two passes)
            const float4* src = (const float4*)(w1 + tid * 128);
            float mx = 0.f;
            for (int i = 0; i < 32; i++) {
                float4 v = src[i];
                mx = fmaxf(mx, fmaxf(fmaxf(fabsf(v.x), fabsf(v.y)), fmaxf(fabsf(v.z), fabsf(v.w))));
            }
            float inv = 127.f / fmaxf(mx, 1e-30f);
            sW1f[tid] = mx * (1.f / 127.f);
            for (int i = 0; i < 32; i++) {
                uint32_t hi, lo;
                quant8(src[i], inv, hi, lo);
                *(uint32_t*)(sm + OFF_W1HI + tid * 144 + i * 4) = hi;
                *(uint32_t*)(sm + OFF_W1LO + tid * 144 + i * 4) = lo;
            }
        }
        sB0[tid] = b0[tid];
        sB1[tid] = b1[tid];
        sW2[tid] = w2[tid];
    }
    const float bias2 = b2[0];
    __syncthreads();

    // ---- lane-fixed addresses ----
    const int q = lane & 7;                     // gather channel chunk
    const int pt_sub = lane >> 3;
    const int lq = lane & 3;                    // mma quad index
    const int lrow = lane >> 2;                 // mma row group (0..7)
    char* fw = sm + OFF_FW + (size_t)wid * 3200;
    char* Fhi = fw;            char* Flo = fw + 768;
    char* Hhi = fw + 1536;     char* Hlo = fw + 2304;
    float* sF = (float*)(fw + 3072);
    // A-fragment LDS offsets (row=lrow(+8), bytes 4*lq (+16))
    const uint32_t aoff = (uint32_t)(lrow * 48 + lq * 4);
    // B-fragment ldsm lane roles
    const int matid = lane >> 3;                // 0..3
    const int lane8 = lane & 7;
    const uint32_t brow_off = (uint32_t)(((matid >> 1) * 8 + lane8));
    const uint32_t kh16 = (uint32_t)((matid & 1) * 16);
    const uint32_t w0base = sb + OFF_W0HI;
    const uint32_t w1base = sb + OFF_W1HI;

    const int gwarp = blockIdx.x * 8 + wid;
    const int nwarp = gridDim.x * 8;

    for (int wt = gwarp; wt < NWTILES; wt += nwarp) {
        const int pbase = wt * 16;

        // ============== gather: 16 points -> int8 hi/lo F rows + sF ==============
        __syncwarp();
#pragma unroll 1
        for (int it = 0; it < 4; it++) {
            const int row = it * 4 + pt_sub;
            const int p = pbase + row;
            const float cx = coords[3 * p + 0];
            const float cy = coords[3 * p + 1];
            const float cz = coords[3 * p + 2];
            const int b = p >> 17;
            float4 acc;
#pragma unroll
            for (int pl = 0; pl < 3; pl++) {
                const float u = (pl == 1) ? cy : cx;
                const float v = (pl == 0) ? cy : cz;
                const float xf = (u + 1.0f) * 127.5f;
                const float yf = (v + 1.0f) * 127.5f;
                const float x0f = floorf(xf), y0f = floorf(yf);
                const float wx = xf - x0f, wy = yf - y0f;
                const int ix0 = (int)x0f, iy0 = (int)y0f;
                const int ix1 = ix0 + 1, iy1 = iy0 + 1;
                const float mx0 = (ix0 >= 0 && ix0 < RDIM) ? 1.0f : 0.0f;
                const float mx1 = (ix1 >= 0 && ix1 < RDIM) ? 1.0f : 0.0f;
                const float my0 = (iy0 >= 0 && iy0 < RDIM) ? 1.0f : 0.0f;
                const float my1 = (iy1 >= 0 && iy1 < RDIM) ? 1.0f : 0.0f;
                const int ix0c = min(max(ix0, 0), RDIM - 1);
                const int ix1c = min(max(ix1, 0), RDIM - 1);
                const int iy0c = min(max(iy0, 0), RDIM - 1);
                const int iy1c = min(max(iy1, 0), RDIM - 1);
                const float w00 = (1.0f - wx) * (1.0f - wy) * mx0 * my0;
                const float w01 = wx * (1.0f - wy) * mx1 * my0;
                const float w10 = (1.0f - wx) * wy * mx0 * my1;
                const float w11 = wx * wy * mx1 * my1;
                const float4* base =
                    (const float4*)(g_tp + ((size_t)(b * 3 + pl) * RDIM * RDIM) * CDIM);
                const float4 a0 = base[(size_t)(iy0c * RDIM + ix0c) * 8 + q];
                const float4 a1 = base[(size_t)(iy0c * RDIM + ix1c) * 8 + q];
                const float4 a2 = base[(size_t)(iy1c * RDIM + ix0c) * 8 + q];
                const float4 a3 = base[(size_t)(iy1c * RDIM + ix1c) * 8 + q];
                float4 s;
                s.x = w00 * a0.x + w01 * a1.x + w10 * a2.x + w11 * a3.x;
                s.y = w00 * a0.y + w01 * a1.y + w10 * a2.y + w11 * a3.y;
                s.z = w00 * a0.z + w01 * a1.z + w10 * a2.z + w11 * a3.z;
                s.w = w00 * a0.w + w01 * a1.w + w10 * a2.w + w11 * a3.w;
                if (pl == 0) acc = s;
                else { acc.x *= s.x; acc.y *= s.y; acc.z *= s.z; acc.w *= s.w; }
            }
            // row max over the 8 lanes of this point
            float mx = fmaxf(fmaxf(fabsf(acc.x), fabsf(acc.y)), fmaxf(fabsf(acc.z), fabsf(acc.w)));
            mx = fmaxf(mx, __shfl_xor_sync(0xFFFFFFFFu, mx, 1));
            mx = fmaxf(mx, __shfl_xor_sync(0xFFFFFFFFu, mx, 2));
            mx = fmaxf(mx, __shfl_xor_sync(0xFFFFFFFFu, mx, 4));
            const float inv = 127.f / fmaxf(mx, 1e-30f);
            uint32_t hi, lo;
            quant8(acc, inv, hi, lo);
            *(uint32_t*)(Fhi + row * 48 + q * 4) = hi;
            *(uint32_t*)(Flo + row * 48 + q * 4) = lo;
            if (q == 0) sF[row] = mx * (1.f / 127.f);
        }
        __syncwarp();

        // ============== layer 0 (k=32, 1 chunk) by n-quarters -> int8 A1 ==============
        uint32_t A0h[4], A0l[4];
        A0h[0] = *(uint32_t*)(Fhi + aoff);        A0h[1] = *(uint32_t*)(Fhi + aoff + 384);
        A0h[2] = *(uint32_t*)(Fhi + aoff + 16);   A0h[3] = *(uint32_t*)(Fhi + aoff + 400);
        A0l[0] = *(uint32_t*)(Flo + aoff);        A0l[1] = *(uint32_t*)(Flo + aoff + 384);
        A0l[2] = *(uint32_t*)(Flo + aoff + 16);   A0l[3] = *(uint32_t*)(Flo + aoff + 400);
        const float sfa = sF[lrow];
        const float sfb = sF[lrow + 8];

        uint32_t A1h[4][4], A1l[4][4];
        float shA[4], shB[4];

#pragma unroll
        for (int q4 = 0; q4 < 4; q4++) {
            int P1[16], P2[16];
#pragma unroll
            for (int i = 0; i < 16; i++) { P1[i] = 0; P2[i] = 0; }
#pragma unroll
            for (int pr = 0; pr < 2; pr++) {
                const uint32_t rb = w0base + (uint32_t)(q4 * 32 + pr * 16 + brow_off) * 48 + kh16;
                uint32_t bh[4], bl[4];
                ldsm4(bh, rb);
                ldsm4(bl, rb + (OFF_W0LO - OFF_W0HI));
                int* d0 = P1 + pr * 8;
                int* d1 = P1 + pr * 8 + 4;
                imma16832(d0, A0h, bh);
                imma16832(d1, A0h, bh + 2);
                imma16832(P2 + pr * 8,     A0h, bl);
                imma16832(P2 + pr * 8 + 4, A0h, bl + 2);
                imma16832(P2 + pr * 8,     A0l, bh);
                imma16832(P2 + pr * 8 + 4, A0l, bh + 2);
            }
            // epilogue0: h = sF*sW0*(P1+P2/254)+b0, relu, quantize per chunk
            float hA[8], hB[8];
#pragma unroll
            for (int nt = 0; nt < 4; nt++) {
                const int colp = q4 * 32 + nt * 8 + 2 * lq;
                const float2 sw = *(const float2*)(sW0f + colp);
                const float2 bb = *(const float2*)(sB0 + colp);
                const int* P1n = P1 + nt * 4;
                const int* P2n = P2 + nt * 4;
                float p0 = (float)P1n[0] + (float)P2n[0] * C254;
                float p1 = (float)P1n[1] + (float)P2n[1] * C254;
                float p2 = (float)P1n[2] + (float)P2n[2] * C254;
                float p3 = (float)P1n[3] + (float)P2n[3] * C254;
                hA[2 * nt]     = fmaxf(fmaf(p0, sfa * sw.x, bb.x), 0.f);
                hA[2 * nt + 1] = fmaxf(fmaf(p1, sfa * sw.y, bb.y), 0.f);
                hB[2 * nt]     = fmaxf(fmaf(p2, sfb * sw.x, bb.x), 0.f);
                hB[2 * nt + 1] = fmaxf(fmaf(p3, sfb * sw.y, bb.y), 0.f);
            }
            float mA = 0.f, mB = 0.f;
#pragma unroll
            for (int i = 0; i < 8; i++) { mA = fmaxf(mA, hA[i]); mB = fmaxf(mB, hB[i]); }
            mA = fmaxf(mA, __shfl_xor_sync(0xFFFFFFFFu, mA, 1));
            mA = fmaxf(mA, __shfl_xor_sync(0xFFFFFFFFu, mA, 2));
            mB = fmaxf(mB, __shfl_xor_sync(0xFFFFFFFFu, mB, 1));
            mB = fmaxf(mB, __shfl_xor_sync(0xFFFFFFFFu, mB, 2));
            const float invA = 127.f / fmaxf(mA, 1e-30f);
            const float invB = 127.f / fmaxf(mB, 1e-30f);
            shA[q4] = mA * (1.f / 127.f);
            shB[q4] = mB * (1.f / 127.f);
#pragma unroll
            for (int nt = 0; nt < 4; nt++) {
                const uint32_t off = (uint32_t)(nt * 8 + 2 * lq);
                float pa0 = hA[2 * nt] * invA,  pa1 = hA[2 * nt + 1] * invA;
                float pb0 = hB[2 * nt] * invB,  pb1 = hB[2 * nt + 1] * invB;
                int a0 = __float2int_rn(pa0), a1 = __float2int_rn(pa1);
                int b0i = __float2int_rn(pb0), b1i = __float2int_rn(pb1);
                int a0l = __float2int_rn((pa0 - (float)a0) * 254.f);
                int a1l = __float2int_rn((pa1 - (float)a1) * 254.f);
                int b0l = __float2int_rn((pb0 - (float)b0i) * 254.f);
                int b1l = __float2int_rn((pb1 - (float)b1i) * 254.f);
                *(unsigned short*)(Hhi + lrow * 48 + off)       = (unsigned short)(__byte_perm(a0, a1, 0x0040));
                *(unsigned short*)(Hhi + (lrow + 8) * 48 + off) = (unsigned short)(__byte_perm(b0i, b1i, 0x0040));
                *(unsigned short*)(Hlo + lrow * 48 + off)       = (unsigned short)(__byte_perm(a0l, a1l, 0x0040));
                *(unsigned short*)(Hlo + (lrow + 8) * 48 + off) = (unsigned short)(__byte_perm(b0l, b1l, 0x0040));
            }
            __syncwarp();
            A1h[q4][0] = *(uint32_t*)(Hhi + aoff);       A1h[q4][1] = *(uint32_t*)(Hhi + aoff + 384);
            A1h[q4][2] = *(uint32_t*)(Hhi + aoff + 16);  A1h[q4][3] = *(uint32_t*)(Hhi + aoff + 400);
            A1l[q4][0] = *(uint32_t*)(Hlo + aoff);       A1l[q4][1] = *(uint32_t*)(Hlo + aoff + 384);
            A1l[q4][2] = *(uint32_t*)(Hlo + aoff + 16);  A1l[q4][3] = *(uint32_t*)(Hlo + aoff + 400);
            __syncwarp();
        }

        // ============== layer 1 (per-chunk scaled GEMMs) + layer 2 ==============
        float acc0 = 0.f, acc1 = 0.f;
#pragma unroll
        for (int q4 = 0; q4 < 4; q4++) {
            float Fq[16];
#pragma unroll
            for (int i = 0; i < 16; i++) Fq[i] = 0.f;
#pragma unroll
            for (int kc = 0; kc < 4; kc++) {
                int P1[16], P2[16];
#pragma unroll
                for (int i = 0; i < 16; i++) { P1[i] = 0; P2[i] = 0; }
#pragma unroll
                for (int pr = 0; pr < 2; pr++) {
                    const uint32_t rb = w1base + (uint32_t)(q4 * 32 + pr * 16 + brow_off) * 144
                                      + (uint32_t)(kc * 32) + kh16;
                    uint32_t bh[4], bl[4];
                    ldsm4(bh, rb);
                    ldsm4(bl, rb + (OFF_W1LO - OFF_W1HI));
                    imma16832(P1 + pr * 8,     A1h[kc], bh);
                    imma16832(P1 + pr * 8 + 4, A1h[kc], bh + 2);
                    imma16832(P2 + pr * 8,     A1h[kc], bl);
                    imma16832(P2 + pr * 8 + 4, A1h[kc], bl + 2);
                    imma16832(P2 + pr * 8,     A1l[kc], bh);
                    imma16832(P2 + pr * 8 + 4, A1l[kc], bh + 2);
                }
                const float scA = shA[kc], scB = shB[kc];
#pragma unroll
                for (int nt = 0; nt < 4; nt++) {
                    const int colp = q4 * 32 + nt * 8 + 2 * lq;
                    const float2 sw = *(const float2*)(sW1f + colp);
                    const int* P1n = P1 + nt * 4;
                    const int* P2n = P2 + nt * 4;
                    Fq[nt * 4 + 0] = fmaf((float)P1n[0] + (float)P2n[0] * C254, scA * sw.x, Fq[nt * 4 + 0]);
                    Fq[nt * 4 + 1] = fmaf((float)P1n[1] + (float)P2n[1] * C254, scA * sw.y, Fq[nt * 4 + 1]);
                    Fq[nt * 4 + 2] = fmaf((float)P1n[2] + (float)P2n[2] * C254, scB * sw.x, Fq[nt * 4 + 2]);
                    Fq[nt * 4 + 3] = fmaf((float)P1n[3] + (float)P2n[3] * C254, scB * sw.y, Fq[nt * 4 + 3]);
                }
            }
            // layer 2 fold for this n-quarter
#pragma unroll
            for (int nt = 0; nt < 4; nt++) {
                const int colp = q4 * 32 + nt * 8 + 2 * lq;
                const float2 bv = *(const float2*)(sB1 + colp);
                const float2 wv = *(const float2*)(sW2 + colp);
                acc0 = fmaf(fmaxf(Fq[nt * 4 + 0] + bv.x, 0.f), wv.x, acc0);
                acc0 = fmaf(fmaxf(Fq[nt * 4 + 1] + bv.y, 0.f), wv.y, acc0);
                acc1 = fmaf(fmaxf(Fq[nt * 4 + 2] + bv.x, 0.f), wv.x, acc1);
                acc1 = fmaf(fmaxf(Fq[nt * 4 + 3] + bv.y, 0.f), wv.y, acc1);
            }
        }

        acc0 += __shfl_xor_sync(0xFFFFFFFFu, acc0, 1);
        acc0 += __shfl_xor_sync(0xFFFFFFFFu, acc0, 2);
        acc1 += __shfl_xor_sync(0xFFFFFFFFu, acc1, 1);
        acc1 += __shfl_xor_sync(0xFFFFFFFFu, acc1, 2);
        if (lq == 0) {
            out[pbase + lrow]     = acc0 + bias2;
            out[pbase + lrow + 8] = acc1 + bias2;
        }
    }
}

// ---------------- host ----------------
extern "C" void kernel_launch(void* const* d_in, const int* in_sizes, int n_in,
                              void* d_out, int out_size) {
    const float* triplanes = (const float*)d_in[0];
    const float* coords    = (const float*)d_in[1];
    const float* w0 = (const float*)d_in[2];
    const float* b0 = (const float*)d_in[3];
    const float* w1 = (const float*)d_in[4];
    const float* b1 = (const float*)d_in[5];
    const float* w2 = (const float*)d_in[6];
    const float* b2 = (const float*)d_in[7];
    float* out = (float*)d_out;

    dim3 tgrid(RDIM / 32, RDIM, 12);
    dim3 tblk(32, 8);
    transpose_planes<<<tgrid, tblk>>>(triplanes);

    static int sms = 0;
    if (sms == 0) {
        cudaDeviceGetAttribute(&sms, cudaDevAttrMultiProcessorCount, 0);
        cudaFuncSetAttribute(fused_triplane_mlp_i8,
                             cudaFuncAttributeMaxDynamicSharedMemorySize, SMEM_BYTES);
    }
    fused_triplane_mlp_i8<<<2 * sms, THREADS, SMEM_BYTES>>>(coords, w0, b0, w1, b1, w2, b2, out);
}

// round 15
// speedup vs baseline: 2.2584x; 2.2584x over previous
#include <cuda_runtime.h>
#include <cuda_bf16.h>
#include <cstdint>

#define RDIM 256
#define CDIM 32
#define NPTS 524288
#define THREADS 256
#define NWTILES (NPTS / 16)        // 32768 warp-tiles of 16 points

// Transposed triplanes scratch: [bp][y][x][c], fp32 (~100.7 MB)
__device__ float g_tp[(size_t)12 * RDIM * RDIM * CDIM];

// ---------------- smem layout (bytes) ----------------
#define OFF_W1HI 0                  // 128 rows * 272B
#define OFF_W1LO 34816
#define OFF_W0HI 69632              // 128 rows * 80B
#define OFF_W0LO 79872
#define OFF_F    90112              // 128 rows * 80B (16 rows per warp)
#define OFF_FLO  100352
#define OFF_B0   110592             // 128 f32
#define OFF_B1   111104
#define OFF_W2   111616
#define SMEM_BYTES 112640

// ---------------- mma / ldmatrix helpers ----------------
__device__ __forceinline__ uint32_t smem_u32(const void* p) {
    uint32_t a;
    asm("{ .reg .u64 t; cvta.to.shared.u64 t, %1; cvt.u32.u64 %0, t; }" : "=r"(a) : "l"(p));
    return a;
}
__device__ __forceinline__ void mma16816(float* d, const uint32_t* a, const uint32_t* b) {
    asm volatile("mma.sync.aligned.m16n8k16.row.col.f32.bf16.bf16.f32 "
                 "{%0,%1,%2,%3}, {%4,%5,%6,%7}, {%8,%9}, {%0,%1,%2,%3};"
                 : "+f"(d[0]), "+f"(d[1]), "+f"(d[2]), "+f"(d[3])
                 : "r"(a[0]), "r"(a[1]), "r"(a[2]), "r"(a[3]), "r"(b[0]), "r"(b[1]));
}
__device__ __forceinline__ void ldsm4(uint32_t* r, uint32_t addr) {
    asm volatile("ldmatrix.sync.aligned.m8n8.x4.shared.b16 {%0,%1,%2,%3}, [%4];"
                 : "=r"(r[0]), "=r"(r[1]), "=r"(r[2]), "=r"(r[3]) : "r"(addr));
}
__device__ __forceinline__ void split2(float v0, float v1, uint32_t& hi, uint32_t& lo) {
    asm("cvt.rn.bf16x2.f32 %0, %1, %2;" : "=r"(hi) : "f"(v1), "f"(v0));
    float f0 = __uint_as_float(hi << 16);
    float f1 = __uint_as_float(hi & 0xFFFF0000u);
    float r0 = v0 - f0, r1 = v1 - f1;
    asm("cvt.rn.bf16x2.f32 %0, %1, %2;" : "=r"(lo) : "f"(r1), "f"(r0));
}

// ---------- Kernel 1: transpose [bp][c][y][x] -> [bp][y][x][c] ----------
// 4 y-rows per block; batched scalar loads (MLP=16), STG.128 stores.
__global__ void transpose_planes(const float* __restrict__ in) {
    __shared__ float t[4][32][33];
    const int tx = threadIdx.x & 31;
    const int ty = threadIdx.x >> 5;          // 0..7
    const int xb = blockIdx.x * 32;
    const int y4 = blockIdx.y * 4;
    const int bp = blockIdx.z;

    const float* src = in + ((size_t)bp * CDIM) * (RDIM * RDIM) + xb + tx;
#pragma unroll
    for (int yi = 0; yi < 4; yi++)
#pragma unroll
        for (int i = 0; i < 4; i++) {
            const int c = ty + i * 8;
            t[yi][c][tx] = src[(size_t)c * (RDIM * RDIM) + (size_t)(y4 + yi) * RDIM];
        }
    __syncthreads();

    const int c4 = (threadIdx.x & 7) * 4;     // 4 contiguous channels
    const int xl = threadIdx.x >> 3;          // 0..31
    float* dst = g_tp + (((size_t)bp * RDIM + y4) * RDIM + xb) * CDIM;
#pragma unroll
    for (int yi = 0; yi < 4; yi++) {
        float4 v;
        v.x = t[yi][c4 + 0][xl];
        v.y = t[yi][c4 + 1][xl];
        v.z = t[yi][c4 + 2][xl];
        v.w = t[yi][c4 + 3][xl];
        *(float4*)(dst + ((size_t)yi * RDIM + xl) * CDIM + c4) = v;
    }
}

// ---------- Kernel 2: gather + bf16 mma.sync MLP (2 CTAs/SM) — R4 baseline ----------
__global__ __launch_bounds__(THREADS, 2)
void fused_triplane_mlp_mma(const float* __restrict__ coords,
                            const float* __restrict__ w0, const float* __restrict__ b0,
                            const float* __restrict__ w1, const float* __restrict__ b1,
                            const float* __restrict__ w2, const float* __restrict__ b2,
                            float* __restrict__ out) {
    extern __shared__ char sm[];
    const uint32_t sb = smem_u32(sm);
    const int tid = threadIdx.x;
    const int wid = tid >> 5;
    const int lane = tid & 31;

    float* sB0 = (float*)(sm + OFF_B0);
    float* sB1 = (float*)(sm + OFF_B1);
    float* sW2 = (float*)(sm + OFF_W2);

    // ---- stage weights: bf16 hi/lo split into padded layouts ----
    for (int i = tid; i < 16384; i += THREADS) {     // w1[g][h], stride 272B
        int g = i >> 7, h = i & 127;
        float v = w1[i];
        __nv_bfloat16 hb = __float2bfloat16(v);
        float res = v - __bfloat162float(hb);
        *(unsigned short*)(sm + OFF_W1HI + g * 272 + h * 2) = *(unsigned short*)&hb;
        __nv_bfloat16 lb = __float2bfloat16(res);
        *(unsigned short*)(sm + OFF_W1LO + g * 272 + h * 2) = *(unsigned short*)&lb;
    }
    for (int i = tid; i < 4096; i += THREADS) {      // w0[j][c], stride 80B
        int j = i >> 5, c = i & 31;
        float v = w0[i];
        __nv_bfloat16 hb = __float2bfloat16(v);
        float res = v - __bfloat162float(hb);
        *(unsigned short*)(sm + OFF_W0HI + j * 80 + c * 2) = *(unsigned short*)&hb;
        __nv_bfloat16 lb = __float2bfloat16(res);
        *(unsigned short*)(sm + OFF_W0LO + j * 80 + c * 2) = *(unsigned short*)&lb;
    }
    if (tid < 128) { sB0[tid] = b0[tid]; sB1[tid] = b1[tid]; sW2[tid] = w2[tid]; }
    const float bias2 = b2[0];
    __syncthreads();

    // ---- lane-fixed ldmatrix base addresses ----
    const int grp = lane >> 3;
    const int idx = lane & 7;
    const uint32_t fA = (uint32_t)((wid * 16 + (lane & 15)) * 80 + (lane >> 4) * 16);
    const uint32_t aHI = sb + OFF_F + fA;
    const uint32_t aLO = sb + OFF_FLO + fA;
    const uint32_t b0off = (uint32_t)(((grp >> 1) * 8 + idx) * 80 + (grp & 1) * 16);
    const uint32_t w0HI = sb + OFF_W0HI + b0off;
    const uint32_t w0LO = sb + OFF_W0LO + b0off;
    const uint32_t b1off = (uint32_t)(((grp >> 1) * 8 + idx) * 272 + (grp & 1) * 16);
    const uint32_t w1HI = sb + OFF_W1HI + b1off;
    const uint32_t w1LO = sb + OFF_W1LO + b1off;
    const int pt_sub = lane >> 3;
    const int q = lane & 7;
    char* fhiw = sm + OFF_F + (size_t)q * 8;
    char* flow = sm + OFF_FLO + (size_t)q * 8;

    const int c2 = 2 * (lane & 3);

    const int gwarp = blockIdx.x * 8 + wid;
    const int nwarp = gridDim.x * 8;

    for (int wt = gwarp; wt < NWTILES; wt += nwarp) {
        const int pbase = wt * 16;

        // ================= gather: 16 points -> F rows (bf16 hi/lo) =================
        __syncwarp();
#pragma unroll 1
        for (int it = 0; it < 4; it++) {
            const int row = it * 4 + pt_sub;
            const int p = pbase + row;
            const float cx = coords[3 * p + 0];
            const float cy = coords[3 * p + 1];
            const float cz = coords[3 * p + 2];
            const int b = p >> 17;
            float4 acc;
#pragma unroll
            for (int pl = 0; pl < 3; pl++) {
                const float u = (pl == 1) ? cy : cx;
                const float v = (pl == 0) ? cy : cz;
                const float xf = (u + 1.0f) * 127.5f;
                const float yf = (v + 1.0f) * 127.5f;
                const float x0f = floorf(xf), y0f = floorf(yf);
                const float wx = xf - x0f, wy = yf - y0f;
                const int ix0 = (int)x0f, iy0 = (int)y0f;
                const int ix1 = ix0 + 1, iy1 = iy0 + 1;
                const float mx0 = (ix0 >= 0 && ix0 < RDIM) ? 1.0f : 0.0f;
                const float mx1 = (ix1 >= 0 && ix1 < RDIM) ? 1.0f : 0.0f;
                const float my0 = (iy0 >= 0 && iy0 < RDIM) ? 1.0f : 0.0f;
                const float my1 = (iy1 >= 0 && iy1 < RDIM) ? 1.0f : 0.0f;
                const int ix0c = min(max(ix0, 0), RDIM - 1);
                const int ix1c = min(max(ix1, 0), RDIM - 1);
                const int iy0c = min(max(iy0, 0), RDIM - 1);
                const int iy1c = min(max(iy1, 0), RDIM - 1);
                const float w00 = (1.0f - wx) * (1.0f - wy) * mx0 * my0;
                const float w01 = wx * (1.0f - wy) * mx1 * my0;
                const float w10 = (1.0f - wx) * wy * mx0 * my1;
                const float w11 = wx * wy * mx1 * my1;
                const float4* base =
                    (const float4*)(g_tp + ((size_t)(b * 3 + pl) * RDIM * RDIM) * CDIM);
                const float4 a0 = base[(size_t)(iy0c * RDIM + ix0c) * 8 + q];
                const float4 a1 = base[(size_t)(iy0c * RDIM + ix1c) * 8 + q];
                const float4 a2 = base[(size_t)(iy1c * RDIM + ix0c) * 8 + q];
                const float4 a3 = base[(size_t)(iy1c * RDIM + ix1c) * 8 + q];
                float4 s;
                s.x = w00 * a0.x + w01 * a1.x + w10 * a2.x + w11 * a3.x;
                s.y = w00 * a0.y + w01 * a1.y + w10 * a2.y + w11 * a3.y;
                s.z = w00 * a0.z + w01 * a1.z + w10 * a2.z + w11 * a3.z;
                s.w = w00 * a0.w + w01 * a1.w + w10 * a2.w + w11 * a3.w;
                if (pl == 0) acc = s;
                else { acc.x *= s.x; acc.y *= s.y; acc.z *= s.z; acc.w *= s.w; }
            }
            uint2 hi, lo;
            split2(acc.x, acc.y, hi.x, lo.x);
            split2(acc.z, acc.w, hi.y, lo.y);
            const int gr = wid * 16 + row;
            *(uint2*)(fhiw + gr * 80) = hi;
            *(uint2*)(flow + gr * 80) = lo;
        }
        __syncwarp();

        // ================= layer 0: D = F(16x32) x W0^T, in two n-halves ============
        uint32_t A0h[2][4], A0l[2][4];
        ldsm4(A0h[0], aHI);       ldsm4(A0h[1], aHI + 32);
        ldsm4(A0l[0], aLO);       ldsm4(A0l[1], aLO + 32);

        uint32_t A1h[8][4], A1l[8][4];
        float D8[8][4];

#pragma unroll
        for (int nh = 0; nh < 2; nh++) {
#pragma unroll
            for (int m = 0; m < 8; m++) { D8[m][0]=0.f; D8[m][1]=0.f; D8[m][2]=0.f; D8[m][3]=0.f; }
#pragma unroll
            for (int ntp = 0; ntp < 4; ntp++) {
                const uint32_t woff = (uint32_t)((nh * 4 + ntp) * (16 * 80));
#pragma unroll
                for (int kf = 0; kf < 2; kf++) {
                    uint32_t bh[4], bl[4];
                    ldsm4(bh, w0HI + woff + kf * 32);
                    ldsm4(bl, w0LO + woff + kf * 32);
                    mma16816(D8[2 * ntp],     A0h[kf], bh);
                    mma16816(D8[2 * ntp],     A0h[kf], bl);
                    mma16816(D8[2 * ntp],     A0l[kf], bh);
                    mma16816(D8[2 * ntp + 1], A0h[kf], bh + 2);
                    mma16816(D8[2 * ntp + 1], A0h[kf], bl + 2);
                    mma16816(D8[2 * ntp + 1], A0l[kf], bh + 2);
                }
            }
            // epilogue0 (half): relu(D + b0) -> bf16 A1 fragments
#pragma unroll
            for (int m = 0; m < 8; m++) {
                const float2 bb = *(const float2*)(sB0 + nh * 64 + 8 * m + c2);
                float v0 = fmaxf(D8[m][0] + bb.x, 0.f);
                float v1 = fmaxf(D8[m][1] + bb.y, 0.f);
                float v2 = fmaxf(D8[m][2] + bb.x, 0.f);
                float v3 = fmaxf(D8[m][3] + bb.y, 0.f);
                const int j = nh * 4 + (m >> 1), h = (m & 1) * 2;
                split2(v0, v1, A1h[j][h],     A1l[j][h]);
                split2(v2, v3, A1h[j][h + 1], A1l[j][h + 1]);
            }
        }

        // ================= layer 1 + layer 2, in two n-halves =================
        float acc0 = 0.f, acc1 = 0.f;
#pragma unroll
        for (int oh = 0; oh < 2; oh++) {
#pragma unroll
            for (int m = 0; m < 8; m++) { D8[m][0]=0.f; D8[m][1]=0.f; D8[m][2]=0.f; D8[m][3]=0.f; }
#pragma unroll
            for (int ntp = 0; ntp < 4; ntp++) {
                const uint32_t woff = (uint32_t)((oh * 4 + ntp) * (16 * 272));
#pragma unroll
                for (int kf = 0; kf < 8; kf++) {
                    uint32_t bh[4], bl[4];
                    ldsm4(bh, w1HI + woff + kf * 32);
                    ldsm4(bl, w1LO + woff + kf * 32);
                    mma16816(D8[2 * ntp],     A1h[kf], bh);
                    mma16816(D8[2 * ntp],     A1h[kf], bl);
                    mma16816(D8[2 * ntp],     A1l[kf], bh);
                    mma16816(D8[2 * ntp + 1], A1h[kf], bh + 2);
                    mma16816(D8[2 * ntp + 1], A1h[kf], bl + 2);
                    mma16816(D8[2 * ntp + 1], A1l[kf], bh + 2);
                }
            }
#pragma unroll
            for (int m = 0; m < 8; m++) {
                const float2 bv = *(const float2*)(sB1 + oh * 64 + 8 * m + c2);
                const float2 wv = *(const float2*)(sW2 + oh * 64 + 8 * m + c2);
                acc0 = fmaf(fmaxf(D8[m][0] + bv.x, 0.f), wv.x, acc0);
                acc0 = fmaf(fmaxf(D8[m][1] + bv.y, 0.f), wv.y, acc0);
                acc1 = fmaf(fmaxf(D8[m][2] + bv.x, 0.f), wv.x, acc1);
                acc1 = fmaf(fmaxf(D8[m][3] + bv.y, 0.f), wv.y, acc1);
            }
        }

        acc0 += __shfl_xor_sync(0xFFFFFFFFu, acc0, 1);
        acc0 += __shfl_xor_sync(0xFFFFFFFFu, acc0, 2);
        acc1 += __shfl_xor_sync(0xFFFFFFFFu, acc1, 1);
        acc1 += __shfl_xor_sync(0xFFFFFFFFu, acc1, 2);
        if ((lane & 3) == 0) {
            const int g = lane >> 2;
            out[pbase + g] = acc0 + bias2;
            out[pbase + g + 8] = acc1 + bias2;
        }
    }
}

// ---------------- host ----------------
extern "C" void kernel_launch(void* const* d_in, const int* in_sizes, int n_in,
                              void* d_out, int out_size) {
    const float* triplanes = (const float*)d_in[0];
    const float* coords    = (const float*)d_in[1];
    const float* w0 = (const float*)d_in[2];
    const float* b0 = (const float*)d_in[3];
    const float* w1 = (const float*)d_in[4];
    const float* b1 = (const float*)d_in[5];
    const float* w2 = (const float*)d_in[6];
    const float* b2 = (const float*)d_in[7];
    float* out = (float*)d_out;

    dim3 tgrid(RDIM / 32, RDIM / 4, 12);
    transpose_planes<<<tgrid, 256>>>(triplanes);

    static int sms = 0;
    if (sms == 0) {
        cudaDeviceGetAttribute(&sms, cudaDevAttrMultiProcessorCount, 0);
        cudaFuncSetAttribute(fused_triplane_mlp_mma,
                             cudaFuncAttributeMaxDynamicSharedMemorySize, SMEM_BYTES);
    }
    fused_triplane_mlp_mma<<<2 * sms, THREADS, SMEM_BYTES>>>(coords, w0, b0, w1, b1, w2, b2, out);
}